// round 1
// baseline (speedup 1.0000x reference)
#include <cuda_runtime.h>
#include <math.h>

// GASPairCopula: sequential GAS(1,1) gaussian-copula log-likelihood scan over T=2^20.
// Parallelized via chunked speculation with warm-up overlap (filter forgets initial
// state at rate <= ALPHA=0.99/step; 0.99^2048 ~ 1.2e-9).

#define T_LEN   (1 << 20)
#define L_CHUNK 256
#define W_WARM  2048
#define P_CHAINS (T_LEN / L_CHUNK)   // 4096

// Scratch (static device globals: allocation-free per harness rules)
__device__ float2 g_sp[T_LEN];          // {sq = x^2+y^2, p = x*y}
__device__ float  g_partial[P_CHAINS];  // per-chain ll partial sums

// ---------------------------------------------------------------------------
// Kernel 1: elementwise precompute of ndtri + data invariants
// ---------------------------------------------------------------------------
__global__ void prep_kernel(const float* __restrict__ u_data,
                            const float* __restrict__ v_data) {
    int stride = gridDim.x * blockDim.x;
    for (int t = blockIdx.x * blockDim.x + threadIdx.x; t < T_LEN; t += stride) {
        float u = fminf(fmaxf(u_data[t], 1e-9f), 1.0f - 1e-9f);
        float v = fminf(fmaxf(v_data[t], 1e-9f), 1.0f - 1e-9f);
        float x = normcdfinvf(u);   // ndtri
        float y = normcdfinvf(v);
        float sq = fmaf(x, x, y * y);
        float p  = x * y;
        g_sp[t] = make_float2(sq, p);
    }
}

// ---------------------------------------------------------------------------
// One GAS step. Returns ll (only meaningful when WANT_LL).
// ---------------------------------------------------------------------------
template <bool WANT_LL>
__device__ __forceinline__ float gas_step(float& f, float& s_var,
                                          float sq, float p,
                                          float omega, float A, float B) {
    float th   = tanhf(f);
    float rho  = 0.999f * th;
    float D    = fmaf(-rho, rho, 1.0f) + 1e-8f;
    float invD = __fdividef(1.0f, D);
    float z    = fmaf(-2.0f * rho, p, sq);

    float ll = 0.0f;
    if (WANT_LL) {
        // -0.5*log(D) - 0.5*(z/D - sq)
        ll = -0.5f * (__logf(D) + fmaf(z, invD, -sq));
    }

    // dll/drho = rho/D + p/D - rho*z/D^2 = ((rho+p) - rho*z*invD) * invD
    float dll   = ((rho + p) - rho * z * invD) * invD;
    float score = dll * (0.999f * fmaf(-th, th, 1.0f));

    s_var = fmaf(0.99f, s_var, (1.0f - 0.99f) * (score * score));
    float scaled = score * rsqrtf(s_var + 1e-8f);

    f = fmaf(B, f - omega, omega);
    f = fmaf(A, scaled, f);
    return ll;
}

// ---------------------------------------------------------------------------
// Kernel 2: P_CHAINS independent speculative chains (1 thread each)
// ---------------------------------------------------------------------------
__global__ void scan_kernel(const float* __restrict__ omega_p,
                            const float* __restrict__ A_p,
                            const float* __restrict__ Blogit_p) {
    int chain = blockIdx.x * blockDim.x + threadIdx.x;
    if (chain >= P_CHAINS) return;

    float omega = *omega_p;
    float A     = *A_p;
    float B     = 1.0f / (1.0f + expf(-*Blogit_p));   // sigmoid

    int start  = chain * L_CHUNK;
    int wstart = start - W_WARM;
    if (wstart < 0) wstart = 0;

    float f = omega, s_var = 1.0f;

    // Warm-up: converge state (no ll accumulation)
    for (int t = wstart; t < start; ++t) {
        float2 sp = g_sp[t];
        gas_step<false>(f, s_var, sp.x, sp.y, omega, A, B);
    }

    // Main chunk: accumulate ll
    float acc = 0.0f;
    #pragma unroll 4
    for (int t = start; t < start + L_CHUNK; ++t) {
        float2 sp = g_sp[t];
        acc += gas_step<true>(f, s_var, sp.x, sp.y, omega, A, B);
    }

    g_partial[chain] = acc;
}

// ---------------------------------------------------------------------------
// Kernel 3: deterministic fixed-order reduction (double accum)
// ---------------------------------------------------------------------------
__global__ void reduce_kernel(float* __restrict__ out) {
    __shared__ double sh[256];
    int tid = threadIdx.x;
    double s = 0.0;
    for (int i = tid; i < P_CHAINS; i += 256)
        s += (double)g_partial[i];
    sh[tid] = s;
    __syncthreads();
    for (int w = 128; w > 0; w >>= 1) {
        if (tid < w) sh[tid] += sh[tid + w];
        __syncthreads();
    }
    if (tid == 0) out[0] = (float)sh[0];
}

// ---------------------------------------------------------------------------
// kernel_launch
// Inputs (metadata order): u_data[T], v_data[T], omega[1], A[1], B_logit[1]
// Output: float[1]
// ---------------------------------------------------------------------------
extern "C" void kernel_launch(void* const* d_in, const int* in_sizes, int n_in,
                              void* d_out, int out_size) {
    const float* u      = (const float*)d_in[0];
    const float* v      = (const float*)d_in[1];
    const float* omega  = (const float*)d_in[2];
    const float* A      = (const float*)d_in[3];
    const float* Blogit = (const float*)d_in[4];
    float* out = (float*)d_out;

    prep_kernel<<<592, 256>>>(u, v);
    scan_kernel<<<P_CHAINS / 64, 64>>>(omega, A, Blogit);
    reduce_kernel<<<1, 256>>>(out);
}

// round 3
// speedup vs baseline: 3.2176x; 3.2176x over previous
#include <cuda_runtime.h>
#include <math.h>

// GASPairCopula: sequential GAS(1,1) gaussian-copula ll scan over T=2^20.
// Chunked speculation: P chains, each re-runs W warm-up steps (filter forgets
// at <= 0.99/step; 0.99^512 ~ 5.8e-3, init state already near-stationary).
// Latency-bound on the dependent chain -> MUFU.TANH + short chain per step.

#define T_LEN   (1 << 20)
#define L_CHUNK 128
#define W_WARM  512
#define P_CHAINS (T_LEN / L_CHUNK)   // 8192

__device__ float2 g_sp[T_LEN];          // {sq = x^2+y^2, p = x*y}
__device__ float  g_partial[P_CHAINS];  // per-chain ll partials

// ---------------------------------------------------------------------------
// fast tanh: single MUFU.TANH (sm_75+), ~2^-10 rel err
// ---------------------------------------------------------------------------
__device__ __forceinline__ float fast_tanh(float x) {
    float r;
    asm("tanh.approx.f32 %0, %1;" : "=f"(r) : "f"(x));
    return r;
}

// ---------------------------------------------------------------------------
// Kernel 1: elementwise ndtri + data invariants (vectorized float4)
// ---------------------------------------------------------------------------
__global__ void prep_kernel(const float* __restrict__ u_data,
                            const float* __restrict__ v_data) {
    int i = blockIdx.x * blockDim.x + threadIdx.x;   // 262144 threads, 4 elems each
    int t0 = i * 4;
    if (t0 >= T_LEN) return;
    float4 u4 = *(const float4*)(u_data + t0);
    float4 v4 = *(const float4*)(v_data + t0);
    float us[4] = {u4.x, u4.y, u4.z, u4.w};
    float vs[4] = {v4.x, v4.y, v4.z, v4.w};
    #pragma unroll
    for (int k = 0; k < 4; ++k) {
        float u = fminf(fmaxf(us[k], 1e-9f), 1.0f - 1e-9f);
        float v = fminf(fmaxf(vs[k], 1e-9f), 1.0f - 1e-9f);
        float x = normcdfinvf(u);
        float y = normcdfinvf(v);
        g_sp[t0 + k] = make_float2(fmaf(x, x, y * y), x * y);
    }
}

// ---------------------------------------------------------------------------
// One GAS step.
// ---------------------------------------------------------------------------
template <bool WANT_LL>
__device__ __forceinline__ float gas_step(float& f, float& s_var,
                                          float sq, float p,
                                          float c0, float A, float B) {
    float th   = fast_tanh(f);
    float rho  = 0.999f * th;
    float D    = fmaf(-rho, rho, 1.0f) + 1e-8f;
    float invD = __fdividef(1.0f, D);      // MUFU.RCP path
    float z    = fmaf(-2.0f * rho, p, sq);

    float ll = 0.0f;
    if (WANT_LL)
        ll = -0.5f * (__logf(D) + fmaf(z, invD, -sq));

    // dll/drho = ((rho+p) - rho*z*invD) * invD
    float rz    = rho * z;                              // parallel w/ invD
    float dll   = ((rho + p) - rz * invD) * invD;
    float score = dll * (0.999f * fmaf(-th, th, 1.0f));

    s_var = fmaf(0.99f, s_var, 0.01f * (score * score));
    float scaled = score * rsqrtf(s_var + 1e-8f);

    // f = omega(1-B) + B*f + A*scaled   (c0 = omega*(1-B))
    f = fmaf(B, f, fmaf(A, scaled, c0));
    return ll;
}

// ---------------------------------------------------------------------------
// Kernel 2: P_CHAINS independent speculative chains (1 thread each).
// block=32 / grid=P/32 spreads ~1-2 warps per SM (latency regime).
// ---------------------------------------------------------------------------
__global__ void scan_kernel(const float* __restrict__ omega_p,
                            const float* __restrict__ A_p,
                            const float* __restrict__ Blogit_p) {
    int chain = blockIdx.x * 32 + threadIdx.x;

    float omega = *omega_p;
    float A     = *A_p;
    float B     = 1.0f / (1.0f + __expf(-*Blogit_p));
    float c0    = omega * (1.0f - B);

    int start  = chain * L_CHUNK;
    int wstart = start - W_WARM;
    if (wstart < 0) wstart = 0;            // chains 0..3: exact prefix replay

    float f = omega, s_var = 1.0f;

    // Warm-up (no ll). 2 steps per float4 load.
    for (int t = wstart; t < start; t += 2) {
        float4 sp = *(const float4*)&g_sp[t];
        gas_step<false>(f, s_var, sp.x, sp.y, c0, A, B);
        gas_step<false>(f, s_var, sp.z, sp.w, c0, A, B);
    }

    // Main chunk
    float acc = 0.0f;
    #pragma unroll 4
    for (int t = start; t < start + L_CHUNK; t += 2) {
        float4 sp = *(const float4*)&g_sp[t];
        acc += gas_step<true>(f, s_var, sp.x, sp.y, c0, A, B);
        acc += gas_step<true>(f, s_var, sp.z, sp.w, c0, A, B);
    }

    g_partial[chain] = acc;
}

// ---------------------------------------------------------------------------
// Kernel 3: deterministic fixed-order reduction (double accum)
// ---------------------------------------------------------------------------
__global__ void reduce_kernel(float* __restrict__ out) {
    __shared__ double sh[256];
    int tid = threadIdx.x;
    double s = 0.0;
    for (int i = tid; i < P_CHAINS; i += 256)
        s += (double)g_partial[i];
    sh[tid] = s;
    __syncthreads();
    for (int w = 128; w > 0; w >>= 1) {
        if (tid < w) sh[tid] += sh[tid + w];
        __syncthreads();
    }
    if (tid == 0) out[0] = (float)sh[0];
}

// ---------------------------------------------------------------------------
extern "C" void kernel_launch(void* const* d_in, const int* in_sizes, int n_in,
                              void* d_out, int out_size) {
    const float* u      = (const float*)d_in[0];
    const float* v      = (const float*)d_in[1];
    const float* omega  = (const float*)d_in[2];
    const float* A      = (const float*)d_in[3];
    const float* Blogit = (const float*)d_in[4];
    float* out = (float*)d_out;

    prep_kernel<<<T_LEN / (256 * 4), 256>>>(u, v);
    scan_kernel<<<P_CHAINS / 32, 32>>>(omega, A, Blogit);
    reduce_kernel<<<1, 256>>>(out);
}

// round 7
// speedup vs baseline: 3.4449x; 1.0706x over previous
#include <cuda_runtime.h>
#include <math.h>

// GASPairCopula: GAS(1,1) gaussian-copula ll scan, T=2^20.
// Chunked speculation (W=512 warm-up, contraction 0.99^512~5.8e-3).
// Scan is latency-bound on the dependent chain (~88 cyc/step after this
// round's fixes); L2-hit load latency hidden via software prefetch.

#define T_LEN   (1 << 20)
#define L_CHUNK 128
#define W_WARM  512
#define P_CHAINS (T_LEN / L_CHUNK)   // 8192

__device__ float2 g_sp[T_LEN];          // {sq = x^2+y^2, p = x*y}
__device__ float  g_partial[P_CHAINS];

// ---- MUFU intrinsics (explicit approx ops, independent of fast-math flags) ----
__device__ __forceinline__ float mufu_tanh(float x) {
    float r; asm("tanh.approx.f32 %0, %1;" : "=f"(r) : "f"(x)); return r;
}
__device__ __forceinline__ float mufu_rcp(float x) {
    float r; asm("rcp.approx.f32 %0, %1;" : "=f"(r) : "f"(x)); return r;
}
__device__ __forceinline__ float mufu_rsqrt(float x) {
    float r; asm("rsqrt.approx.f32 %0, %1;" : "=f"(r) : "f"(x)); return r;
}
__device__ __forceinline__ float mufu_lg2(float x) {
    float r; asm("lg2.approx.f32 %0, %1;" : "=f"(r) : "f"(x)); return r;
}

// ---------------------------------------------------------------------------
// Kernel 1: ndtri + data invariants
// ---------------------------------------------------------------------------
__global__ void prep_kernel(const float* __restrict__ u_data,
                            const float* __restrict__ v_data) {
    int i = blockIdx.x * blockDim.x + threadIdx.x;
    int t0 = i * 4;
    if (t0 >= T_LEN) return;
    float4 u4 = *(const float4*)(u_data + t0);
    float4 v4 = *(const float4*)(v_data + t0);
    float us[4] = {u4.x, u4.y, u4.z, u4.w};
    float vs[4] = {v4.x, v4.y, v4.z, v4.w};
    #pragma unroll
    for (int k = 0; k < 4; ++k) {
        float u = fminf(fmaxf(us[k], 1e-9f), 1.0f - 1e-9f);
        float v = fminf(fmaxf(vs[k], 1e-9f), 1.0f - 1e-9f);
        float x = normcdfinvf(u);
        float y = normcdfinvf(v);
        g_sp[t0 + k] = make_float2(fmaf(x, x, y * y), x * y);
    }
}

// ---------------------------------------------------------------------------
// One GAS step. q = s_var + 1e-8 iterated directly.
// acc accumulates (log D + z/D - sq), scaled by -0.5 at the end.
// ---------------------------------------------------------------------------
__device__ __forceinline__ void gas_step(float& f, float& q, float& acc,
                                         bool want_ll,
                                         float sq, float p,
                                         float c0, float A, float B) {
    float th   = mufu_tanh(f);
    float fb   = fmaf(B, f, c0);                      // || with tanh
    float rho  = 0.999f * th;
    float g    = 0.999f * fmaf(-th, th, 1.0f);        // off critical path
    float D    = fmaf(-rho, rho, 1.00000001f);        // 1 - rho^2 + 1e-8
    float invD = mufu_rcp(D);
    float n2p  = -(p + p);                            // data-only, early
    float z    = fmaf(rho, n2p, sq);
    float rz   = rho * z;
    float rp   = rho + p;

    if (want_ll) {
        float llt = fmaf(mufu_lg2(D), 0.6931472f, fmaf(z, invD, -sq));
        acc += llt;
    }

    float u     = fmaf(-rz, invD, rp);
    float dll   = u * invD;
    float score = dll * g;
    float s2    = score * score;
    q = fmaf(0.99f, q, fmaf(0.01f, s2, 1e-10f));      // = s_var_new + 1e-8
    float scaled = score * mufu_rsqrt(q);
    f = fmaf(A, scaled, fb);
}

// ---------------------------------------------------------------------------
// Kernel 2: speculative chains, software-pipelined loads.
// Unified warm+main loop; ll predicated on t >= start.
// All (start - wstart) lengths and L_CHUNK are multiples of 4.
// ---------------------------------------------------------------------------
__global__ void scan_kernel(const float* __restrict__ omega_p,
                            const float* __restrict__ A_p,
                            const float* __restrict__ Blogit_p) {
    int chain = blockIdx.x * 32 + threadIdx.x;

    float omega = *omega_p;
    float A     = *A_p;
    float B     = 1.0f / (1.0f + __expf(-*Blogit_p));
    float c0    = omega * (1.0f - B);

    int start  = chain * L_CHUNK;
    int wstart = start - W_WARM;
    if (wstart < 0) wstart = 0;
    int end = start + L_CHUNK;

    float f = omega, q = 1.0f + 1e-8f, acc = 0.0f;

    // Prime the pipeline: two float4 = 4 steps of data.
    const float4* sp4 = (const float4*)g_sp;          // sp4[i] = steps {2i, 2i+1}
    int i    = wstart >> 1;                           // float4 index
    int iend = end >> 1;
    float4 a = sp4[i];
    float4 b = sp4[i + 1];

    for (int t = wstart; t < end; t += 4, i += 2) {
        // Prefetch next iteration (clamped; redundant reload on last iter).
        int ip = i + 2;
        if (ip + 1 >= iend) ip = iend - 2;
        float4 na = sp4[ip];
        float4 nb = sp4[ip + 1];

        gas_step(f, q, acc, t     >= start, a.x, a.y, c0, A, B);
        gas_step(f, q, acc, t + 1 >= start, a.z, a.w, c0, A, B);
        gas_step(f, q, acc, t + 2 >= start, b.x, b.y, c0, A, B);
        gas_step(f, q, acc, t + 3 >= start, b.z, b.w, c0, A, B);

        a = na; b = nb;
    }

    g_partial[chain] = -0.5f * acc;
}

// ---------------------------------------------------------------------------
// Kernel 3: deterministic fixed-order reduction
// ---------------------------------------------------------------------------
__global__ void reduce_kernel(float* __restrict__ out) {
    __shared__ double sh[256];
    int tid = threadIdx.x;
    double s = 0.0;
    for (int i = tid; i < P_CHAINS; i += 256)
        s += (double)g_partial[i];
    sh[tid] = s;
    __syncthreads();
    for (int w = 128; w > 0; w >>= 1) {
        if (tid < w) sh[tid] += sh[tid + w];
        __syncthreads();
    }
    if (tid == 0) out[0] = (float)sh[0];
}

// ---------------------------------------------------------------------------
extern "C" void kernel_launch(void* const* d_in, const int* in_sizes, int n_in,
                              void* d_out, int out_size) {
    const float* u      = (const float*)d_in[0];
    const float* v      = (const float*)d_in[1];
    const float* omega  = (const float*)d_in[2];
    const float* A      = (const float*)d_in[3];
    const float* Blogit = (const float*)d_in[4];
    float* out = (float*)d_out;

    prep_kernel<<<T_LEN / (256 * 4), 256>>>(u, v);
    scan_kernel<<<P_CHAINS / 32, 32>>>(omega, A, Blogit);
    reduce_kernel<<<1, 256>>>(out);
}

// round 8
// speedup vs baseline: 4.3610x; 1.2659x over previous
#include <cuda_runtime.h>
#include <math.h>

// GASPairCopula: GAS(1,1) gaussian-copula ll scan, T=2^20.
// Chunked speculation (W=512 warm-up, contraction 0.99^512 ~ 5.8e-3).
// R8: block-level smem staging. A block's 32 chains cover a contiguous
// 4608-step span; load it coalesced into smem once, then the latency-bound
// chain reads LDS (29 cyc, skewed banks) instead of 32-line uncoalesced LDG.

#define T_LEN    (1 << 20)
#define L_CHUNK  128
#define W_WARM   512
#define P_CHAINS (T_LEN / L_CHUNK)            // 8192
#define SPAN     (W_WARM + 32 * L_CHUNK)      // 4608 steps per block
#define SM_ELEMS (SPAN + (SPAN >> 7) + 4)     // skewed capacity

__device__ float2 g_sp[T_LEN];                // {sq = x^2+y^2, p = x*y}
__device__ float  g_partial[P_CHAINS];

// ---- MUFU intrinsics ----
__device__ __forceinline__ float mufu_tanh(float x) {
    float r; asm("tanh.approx.f32 %0, %1;" : "=f"(r) : "f"(x)); return r;
}
__device__ __forceinline__ float mufu_rcp(float x) {
    float r; asm("rcp.approx.f32 %0, %1;" : "=f"(r) : "f"(x)); return r;
}
__device__ __forceinline__ float mufu_rsqrt(float x) {
    float r; asm("rsqrt.approx.f32 %0, %1;" : "=f"(r) : "f"(x)); return r;
}
__device__ __forceinline__ float mufu_lg2(float x) {
    float r; asm("lg2.approx.f32 %0, %1;" : "=f"(r) : "f"(x)); return r;
}

__device__ __forceinline__ int sidx(int t) { return t + (t >> 7); }  // bank skew

// ---------------------------------------------------------------------------
// Kernel 1: ndtri + data invariants
// ---------------------------------------------------------------------------
__global__ void prep_kernel(const float* __restrict__ u_data,
                            const float* __restrict__ v_data) {
    int i = blockIdx.x * blockDim.x + threadIdx.x;
    int t0 = i * 4;
    if (t0 >= T_LEN) return;
    float4 u4 = *(const float4*)(u_data + t0);
    float4 v4 = *(const float4*)(v_data + t0);
    float us[4] = {u4.x, u4.y, u4.z, u4.w};
    float vs[4] = {v4.x, v4.y, v4.z, v4.w};
    #pragma unroll
    for (int k = 0; k < 4; ++k) {
        float u = fminf(fmaxf(us[k], 1e-9f), 1.0f - 1e-9f);
        float v = fminf(fmaxf(vs[k], 1e-9f), 1.0f - 1e-9f);
        float x = normcdfinvf(u);
        float y = normcdfinvf(v);
        g_sp[t0 + k] = make_float2(fmaf(x, x, y * y), x * y);
    }
}

// ---------------------------------------------------------------------------
// One GAS step (q = s_var + 1e-8 iterated directly; ll unscaled, *-0.5 at end)
// ---------------------------------------------------------------------------
__device__ __forceinline__ void gas_step(float& f, float& q, float& acc,
                                         bool want_ll,
                                         float sq, float p,
                                         float c0, float A, float B) {
    float th   = mufu_tanh(f);
    float fb   = fmaf(B, f, c0);                   // || with tanh
    float rho  = 0.999f * th;
    float g    = 0.999f * fmaf(-th, th, 1.0f);
    float D    = fmaf(-rho, rho, 1.00000001f);     // 1 - rho^2 + 1e-8
    float invD = mufu_rcp(D);
    float n2p  = -(p + p);
    float z    = fmaf(rho, n2p, sq);
    float rz   = rho * z;
    float rp   = rho + p;

    if (want_ll)
        acc += fmaf(mufu_lg2(D), 0.6931472f, fmaf(z, invD, -sq));

    float u     = fmaf(-rz, invD, rp);
    float dll   = u * invD;
    float score = dll * g;
    float s2    = score * score;
    q = fmaf(0.99f, q, fmaf(0.01f, s2, 1e-10f));   // s_var_new + 1e-8
    float scaled = score * mufu_rsqrt(q);
    f = fmaf(A, scaled, fb);
}

// ---------------------------------------------------------------------------
// Kernel 2: 32 chains per block, contiguous span staged in smem.
// ---------------------------------------------------------------------------
__global__ void scan_kernel(const float* __restrict__ omega_p,
                            const float* __restrict__ A_p,
                            const float* __restrict__ Blogit_p) {
    __shared__ float2 sm[SM_ELEMS];

    int blk = blockIdx.x;
    int block_start = blk * 32 * L_CHUNK;
    int lo = block_start - W_WARM;
    if (lo < 0) lo = 0;                            // block 0 only
    int hi = block_start + 32 * L_CHUNK;
    int n  = hi - lo;                              // 4096 (blk 0) or 4608; even

    // Coalesced staging: float4 = 2 float2 elements, store skewed.
    const float4* src = (const float4*)(g_sp + lo);
    for (int j4 = threadIdx.x; j4 < (n >> 1); j4 += 32) {
        float4 w = src[j4];
        int t0 = j4 * 2;
        sm[sidx(t0)]     = make_float2(w.x, w.y);
        sm[sidx(t0 + 1)] = make_float2(w.z, w.w);
    }
    __syncthreads();

    float omega = *omega_p;
    float A     = *A_p;
    float B     = 1.0f / (1.0f + __expf(-*Blogit_p));
    float c0    = omega * (1.0f - B);

    int chain  = blk * 32 + threadIdx.x;
    int start  = chain * L_CHUNK;
    int wstart = start - W_WARM;
    if (wstart < 0) wstart = 0;
    int end = start + L_CHUNK;

    int j      = wstart - lo;                      // local smem step index
    int jend   = end - lo;
    int jstart = start - lo;                       // ll turns on here

    float f = omega, q = 1.0f + 1e-8f, acc = 0.0f;

    // Register prefetch: one group (4 steps) ahead.
    float2 d0 = sm[sidx(j)],     d1 = sm[sidx(j + 1)];
    float2 d2 = sm[sidx(j + 2)], d3 = sm[sidx(j + 3)];

    for (; j < jend; j += 4) {
        int jp = j + 4;
        if (jp > jend - 4) jp = jend - 4;          // clamp (redundant reload ok)
        float2 n0 = sm[sidx(jp)],     n1 = sm[sidx(jp + 1)];
        float2 n2 = sm[sidx(jp + 2)], n3 = sm[sidx(jp + 3)];

        gas_step(f, q, acc, j     >= jstart, d0.x, d0.y, c0, A, B);
        gas_step(f, q, acc, j + 1 >= jstart, d1.x, d1.y, c0, A, B);
        gas_step(f, q, acc, j + 2 >= jstart, d2.x, d2.y, c0, A, B);
        gas_step(f, q, acc, j + 3 >= jstart, d3.x, d3.y, c0, A, B);

        d0 = n0; d1 = n1; d2 = n2; d3 = n3;
    }

    g_partial[chain] = -0.5f * acc;
}

// ---------------------------------------------------------------------------
// Kernel 3: deterministic fixed-order reduction
// ---------------------------------------------------------------------------
__global__ void reduce_kernel(float* __restrict__ out) {
    __shared__ double sh[256];
    int tid = threadIdx.x;
    double s = 0.0;
    for (int i = tid; i < P_CHAINS; i += 256)
        s += (double)g_partial[i];
    sh[tid] = s;
    __syncthreads();
    for (int w = 128; w > 0; w >>= 1) {
        if (tid < w) sh[tid] += sh[tid + w];
        __syncthreads();
    }
    if (tid == 0) out[0] = (float)sh[0];
}

// ---------------------------------------------------------------------------
extern "C" void kernel_launch(void* const* d_in, const int* in_sizes, int n_in,
                              void* d_out, int out_size) {
    const float* u      = (const float*)d_in[0];
    const float* v      = (const float*)d_in[1];
    const float* omega  = (const float*)d_in[2];
    const float* A      = (const float*)d_in[3];
    const float* Blogit = (const float*)d_in[4];
    float* out = (float*)d_out;

    prep_kernel<<<T_LEN / (256 * 4), 256>>>(u, v);
    scan_kernel<<<P_CHAINS / 32, 32>>>(omega, A, Blogit);
    reduce_kernel<<<1, 256>>>(out);
}

// round 10
// speedup vs baseline: 4.4978x; 1.0314x over previous
#include <cuda_runtime.h>
#include <math.h>

// GASPairCopula: GAS(1,1) gaussian-copula ll scan, T=2^20.
// Chunked speculation (W=512 warm-up, contraction 0.99^512 ~ 5.8e-3).
// R9: 128 chains/block (4 warps -> one chain-warp per SMSP, 64 blocks =
// 1 block/SM, no SMSP/MUFU contention), unified 135KB smem span staged
// coalesced by all 128 threads; chain retimed to ~80 cyc/step.

#define T_LEN    (1 << 20)
#define L_CHUNK  128
#define W_WARM   512
#define P_CHAINS (T_LEN / L_CHUNK)                 // 8192
#define CPB      128                               // chains per block
#define NBLK     (P_CHAINS / CPB)                  // 64
#define SPAN     (W_WARM + CPB * L_CHUNK)          // 16896 steps
#define SM_ELEMS (SPAN + (SPAN >> 7) + 4)          // skewed capacity
#define SMEM_BYTES (SM_ELEMS * sizeof(float2))

__device__ float2 g_sp[T_LEN];                     // {sq = x^2+y^2, p = x*y}
__device__ float  g_partial[P_CHAINS];

// ---- MUFU intrinsics ----
__device__ __forceinline__ float mufu_tanh(float x) {
    float r; asm("tanh.approx.f32 %0, %1;" : "=f"(r) : "f"(x)); return r;
}
__device__ __forceinline__ float mufu_rcp(float x) {
    float r; asm("rcp.approx.f32 %0, %1;" : "=f"(r) : "f"(x)); return r;
}
__device__ __forceinline__ float mufu_rsqrt(float x) {
    float r; asm("rsqrt.approx.f32 %0, %1;" : "=f"(r) : "f"(x)); return r;
}
__device__ __forceinline__ float mufu_lg2(float x) {
    float r; asm("lg2.approx.f32 %0, %1;" : "=f"(r) : "f"(x)); return r;
}

__device__ __forceinline__ int sidx(int t) { return t + (t >> 7); }  // bank skew

// ---------------------------------------------------------------------------
// Kernel 1: ndtri + data invariants (2 elems/thread for high occupancy)
// ---------------------------------------------------------------------------
__global__ void prep_kernel(const float* __restrict__ u_data,
                            const float* __restrict__ v_data) {
    int i = blockIdx.x * blockDim.x + threadIdx.x;
    int t0 = i * 2;
    if (t0 >= T_LEN) return;
    float2 u2 = *(const float2*)(u_data + t0);
    float2 v2 = *(const float2*)(v_data + t0);
    float us[2] = {u2.x, u2.y};
    float vs[2] = {v2.x, v2.y};
    #pragma unroll
    for (int k = 0; k < 2; ++k) {
        float u = fminf(fmaxf(us[k], 1e-9f), 1.0f - 1e-9f);
        float v = fminf(fmaxf(vs[k], 1e-9f), 1.0f - 1e-9f);
        float x = normcdfinvf(u);
        float y = normcdfinvf(v);
        g_sp[t0 + k] = make_float2(fmaf(x, x, y * y), x * y);
    }
}

// ---------------------------------------------------------------------------
// One GAS step, retimed (~80 cyc f->f critical path).
// q = s_var + 1e-8 iterated directly; ll unscaled, *-0.5 at the end.
// ---------------------------------------------------------------------------
__device__ __forceinline__ void gas_step(float& f, float& q, float& acc,
                                         bool want_ll,
                                         float sq, float p,
                                         float c0, float A, float B) {
    float th   = mufu_tanh(f);                     // @16
    float fb   = fmaf(B, f, c0);                   // || with tanh
    float rho  = 0.999f * th;                      // @20
    float g    = 0.999f * fmaf(-th, th, 1.0f);     // @24 (off chain)
    float Ag   = A * g;                            // @28 (off chain)
    float D    = fmaf(-rho, rho, 1.00000001f);     // @24: 1 - rho^2 + 1e-8
    float invD = mufu_rcp(D);                      // @40
    float n2p  = -(p + p);                         // data-only
    float z    = fmaf(rho, n2p, sq);               // @28
    float rz   = rho * z;                          // @32
    float rp   = rho + p;                          // @24

    if (want_ll)
        acc += fmaf(mufu_lg2(D), 0.6931472f, fmaf(z, invD, -sq));

    float u      = fmaf(-rz, invD, rp);            // @44
    float dll    = u * invD;                       // @48
    float score  = dll * g;                        // @52
    float Ascore = dll * Ag;                       // @52 (parallel)
    float s2     = score * score;                  // @56
    float qb     = fmaf(0.99f, q, 1e-10f);         // early: q loop-carried
    q = fmaf(0.01f, s2, qb);                       // @60  (= s_var_new + 1e-8)
    float rs = mufu_rsqrt(q);                      // @76
    f = fmaf(Ascore, rs, fb);                      // @80
}

// ---------------------------------------------------------------------------
// Kernel 2: 128 chains per block (4 warps, one per SMSP), 64 blocks.
// Contiguous 16896-step span staged into dynamic smem, coalesced.
// ---------------------------------------------------------------------------
__global__ void scan_kernel(const float* __restrict__ omega_p,
                            const float* __restrict__ A_p,
                            const float* __restrict__ Blogit_p) {
    extern __shared__ float2 sm[];

    int blk  = blockIdx.x;
    int base = blk * CPB * L_CHUNK;                // 16384 per block
    int lo   = base - W_WARM;
    if (lo < 0) lo = 0;                            // block 0 only
    int hi = base + CPB * L_CHUNK;
    int n  = hi - lo;                              // 16384 or 16896

    // Coalesced staging: float4 = 2 float2 steps, skewed store.
    // n/2 is a multiple of 128 -> no remainder handling.
    const float4* src = (const float4*)(g_sp + lo);
    int nf4 = n >> 1;
    #pragma unroll 4
    for (int j4 = threadIdx.x; j4 < nf4; j4 += CPB) {
        float4 w = src[j4];
        int t0 = j4 * 2;
        sm[sidx(t0)]     = make_float2(w.x, w.y);
        sm[sidx(t0 + 1)] = make_float2(w.z, w.w);
    }
    __syncthreads();

    float omega = *omega_p;
    float A     = *A_p;
    float B     = 1.0f / (1.0f + __expf(-*Blogit_p));
    float c0    = omega * (1.0f - B);

    int chain  = blk * CPB + threadIdx.x;
    int start  = chain * L_CHUNK;
    int wstart = start - W_WARM;
    if (wstart < 0) wstart = 0;
    int end = start + L_CHUNK;

    int j      = wstart - lo;
    int jend   = end - lo;
    int jstart = start - lo;                       // ll turns on here

    float f = omega, q = 1.0f + 1e-8f, acc = 0.0f;

    // Register prefetch one 4-step group ahead (LDS lat 29 << ~340 cyc/group).
    float2 d0 = sm[sidx(j)],     d1 = sm[sidx(j + 1)];
    float2 d2 = sm[sidx(j + 2)], d3 = sm[sidx(j + 3)];

    for (; j < jend; j += 4) {
        int jp = j + 4;
        if (jp > jend - 4) jp = jend - 4;          // clamp (redundant reload ok)
        float2 n0 = sm[sidx(jp)],     n1 = sm[sidx(jp + 1)];
        float2 n2 = sm[sidx(jp + 2)], n3 = sm[sidx(jp + 3)];

        gas_step(f, q, acc, j     >= jstart, d0.x, d0.y, c0, A, B);
        gas_step(f, q, acc, j + 1 >= jstart, d1.x, d1.y, c0, A, B);
        gas_step(f, q, acc, j + 2 >= jstart, d2.x, d2.y, c0, A, B);
        gas_step(f, q, acc, j + 3 >= jstart, d3.x, d3.y, c0, A, B);

        d0 = n0; d1 = n1; d2 = n2; d3 = n3;
    }

    g_partial[chain] = -0.5f * acc;
}

// ---------------------------------------------------------------------------
// Kernel 3: deterministic fixed-order reduction
// ---------------------------------------------------------------------------
__global__ void reduce_kernel(float* __restrict__ out) {
    __shared__ double sh[256];
    int tid = threadIdx.x;
    double s = 0.0;
    for (int i = tid; i < P_CHAINS; i += 256)
        s += (double)g_partial[i];
    sh[tid] = s;
    __syncthreads();
    for (int w = 128; w > 0; w >>= 1) {
        if (tid < w) sh[tid] += sh[tid + w];
        __syncthreads();
    }
    if (tid == 0) out[0] = (float)sh[0];
}

// ---------------------------------------------------------------------------
extern "C" void kernel_launch(void* const* d_in, const int* in_sizes, int n_in,
                              void* d_out, int out_size) {
    const float* u      = (const float*)d_in[0];
    const float* v      = (const float*)d_in[1];
    const float* omega  = (const float*)d_in[2];
    const float* A      = (const float*)d_in[3];
    const float* Blogit = (const float*)d_in[4];
    float* out = (float*)d_out;

    // Dynamic smem opt-in (host-side attribute, idempotent, not a stream op).
    cudaFuncSetAttribute(scan_kernel,
                         cudaFuncAttributeMaxDynamicSharedMemorySize,
                         (int)SMEM_BYTES);

    prep_kernel<<<T_LEN / (256 * 2), 256>>>(u, v);
    scan_kernel<<<NBLK, CPB, SMEM_BYTES>>>(omega, A, Blogit);
    reduce_kernel<<<1, 256>>>(out);
}

// round 13
// speedup vs baseline: 4.5153x; 1.0039x over previous
#include <cuda_runtime.h>
#include <math.h>

// GASPairCopula: GAS(1,1) gaussian-copula ll scan, T=2^20.
// Chunked speculation (W=512 warm-up, contraction 0.99^512 ~ 5.8e-3).
// R9: 128 chains/block (4 warps -> one chain-warp per SMSP, 64 blocks =
// 1 block/SM, no SMSP/MUFU contention), unified 135KB smem span staged
// coalesced by all 128 threads; chain retimed to ~80 cyc/step.

#define T_LEN    (1 << 20)
#define L_CHUNK  128
#define W_WARM   512
#define P_CHAINS (T_LEN / L_CHUNK)                 // 8192
#define CPB      128                               // chains per block
#define NBLK     (P_CHAINS / CPB)                  // 64
#define SPAN     (W_WARM + CPB * L_CHUNK)          // 16896 steps
#define SM_ELEMS (SPAN + (SPAN >> 7) + 4)          // skewed capacity
#define SMEM_BYTES (SM_ELEMS * sizeof(float2))

__device__ float2 g_sp[T_LEN];                     // {sq = x^2+y^2, p = x*y}
__device__ float  g_partial[P_CHAINS];

// ---- MUFU intrinsics ----
__device__ __forceinline__ float mufu_tanh(float x) {
    float r; asm("tanh.approx.f32 %0, %1;" : "=f"(r) : "f"(x)); return r;
}
__device__ __forceinline__ float mufu_rcp(float x) {
    float r; asm("rcp.approx.f32 %0, %1;" : "=f"(r) : "f"(x)); return r;
}
__device__ __forceinline__ float mufu_rsqrt(float x) {
    float r; asm("rsqrt.approx.f32 %0, %1;" : "=f"(r) : "f"(x)); return r;
}
__device__ __forceinline__ float mufu_lg2(float x) {
    float r; asm("lg2.approx.f32 %0, %1;" : "=f"(r) : "f"(x)); return r;
}

__device__ __forceinline__ int sidx(int t) { return t + (t >> 7); }  // bank skew

// ---------------------------------------------------------------------------
// Kernel 1: ndtri + data invariants (2 elems/thread for high occupancy)
// ---------------------------------------------------------------------------
__global__ void prep_kernel(const float* __restrict__ u_data,
                            const float* __restrict__ v_data) {
    int i = blockIdx.x * blockDim.x + threadIdx.x;
    int t0 = i * 2;
    if (t0 >= T_LEN) return;
    float2 u2 = *(const float2*)(u_data + t0);
    float2 v2 = *(const float2*)(v_data + t0);
    float us[2] = {u2.x, u2.y};
    float vs[2] = {v2.x, v2.y};
    #pragma unroll
    for (int k = 0; k < 2; ++k) {
        float u = fminf(fmaxf(us[k], 1e-9f), 1.0f - 1e-9f);
        float v = fminf(fmaxf(vs[k], 1e-9f), 1.0f - 1e-9f);
        float x = normcdfinvf(u);
        float y = normcdfinvf(v);
        g_sp[t0 + k] = make_float2(fmaf(x, x, y * y), x * y);
    }
}

// ---------------------------------------------------------------------------
// One GAS step, retimed (~80 cyc f->f critical path).
// q = s_var + 1e-8 iterated directly; ll unscaled, *-0.5 at the end.
// ---------------------------------------------------------------------------
__device__ __forceinline__ void gas_step(float& f, float& q, float& acc,
                                         bool want_ll,
                                         float sq, float p,
                                         float c0, float A, float B) {
    float th   = mufu_tanh(f);                     // @16
    float fb   = fmaf(B, f, c0);                   // || with tanh
    float rho  = 0.999f * th;                      // @20
    float g    = 0.999f * fmaf(-th, th, 1.0f);     // @24 (off chain)
    float Ag   = A * g;                            // @28 (off chain)
    float D    = fmaf(-rho, rho, 1.00000001f);     // @24: 1 - rho^2 + 1e-8
    float invD = mufu_rcp(D);                      // @40
    float n2p  = -(p + p);                         // data-only
    float z    = fmaf(rho, n2p, sq);               // @28
    float rz   = rho * z;                          // @32
    float rp   = rho + p;                          // @24

    if (want_ll)
        acc += fmaf(mufu_lg2(D), 0.6931472f, fmaf(z, invD, -sq));

    float u      = fmaf(-rz, invD, rp);            // @44
    float dll    = u * invD;                       // @48
    float score  = dll * g;                        // @52
    float Ascore = dll * Ag;                       // @52 (parallel)
    float s2     = score * score;                  // @56
    float qb     = fmaf(0.99f, q, 1e-10f);         // early: q loop-carried
    q = fmaf(0.01f, s2, qb);                       // @60  (= s_var_new + 1e-8)
    float rs = mufu_rsqrt(q);                      // @76
    f = fmaf(Ascore, rs, fb);                      // @80
}

// ---------------------------------------------------------------------------
// Kernel 2: 128 chains per block (4 warps, one per SMSP), 64 blocks.
// Contiguous 16896-step span staged into dynamic smem, coalesced.
// ---------------------------------------------------------------------------
__global__ void scan_kernel(const float* __restrict__ omega_p,
                            const float* __restrict__ A_p,
                            const float* __restrict__ Blogit_p) {
    extern __shared__ float2 sm[];

    int blk  = blockIdx.x;
    int base = blk * CPB * L_CHUNK;                // 16384 per block
    int lo   = base - W_WARM;
    if (lo < 0) lo = 0;                            // block 0 only
    int hi = base + CPB * L_CHUNK;
    int n  = hi - lo;                              // 16384 or 16896

    // Coalesced staging: float4 = 2 float2 steps, skewed store.
    // n/2 is a multiple of 128 -> no remainder handling.
    const float4* src = (const float4*)(g_sp + lo);
    int nf4 = n >> 1;
    #pragma unroll 4
    for (int j4 = threadIdx.x; j4 < nf4; j4 += CPB) {
        float4 w = src[j4];
        int t0 = j4 * 2;
        sm[sidx(t0)]     = make_float2(w.x, w.y);
        sm[sidx(t0 + 1)] = make_float2(w.z, w.w);
    }
    __syncthreads();

    float omega = *omega_p;
    float A     = *A_p;
    float B     = 1.0f / (1.0f + __expf(-*Blogit_p));
    float c0    = omega * (1.0f - B);

    int chain  = blk * CPB + threadIdx.x;
    int start  = chain * L_CHUNK;
    int wstart = start - W_WARM;
    if (wstart < 0) wstart = 0;
    int end = start + L_CHUNK;

    int j      = wstart - lo;
    int jend   = end - lo;
    int jstart = start - lo;                       // ll turns on here

    float f = omega, q = 1.0f + 1e-8f, acc = 0.0f;

    // Register prefetch one 4-step group ahead (LDS lat 29 << ~340 cyc/group).
    float2 d0 = sm[sidx(j)],     d1 = sm[sidx(j + 1)];
    float2 d2 = sm[sidx(j + 2)], d3 = sm[sidx(j + 3)];

    for (; j < jend; j += 4) {
        int jp = j + 4;
        if (jp > jend - 4) jp = jend - 4;          // clamp (redundant reload ok)
        float2 n0 = sm[sidx(jp)],     n1 = sm[sidx(jp + 1)];
        float2 n2 = sm[sidx(jp + 2)], n3 = sm[sidx(jp + 3)];

        gas_step(f, q, acc, j     >= jstart, d0.x, d0.y, c0, A, B);
        gas_step(f, q, acc, j + 1 >= jstart, d1.x, d1.y, c0, A, B);
        gas_step(f, q, acc, j + 2 >= jstart, d2.x, d2.y, c0, A, B);
        gas_step(f, q, acc, j + 3 >= jstart, d3.x, d3.y, c0, A, B);

        d0 = n0; d1 = n1; d2 = n2; d3 = n3;
    }

    g_partial[chain] = -0.5f * acc;
}

// ---------------------------------------------------------------------------
// Kernel 3: deterministic fixed-order reduction
// ---------------------------------------------------------------------------
__global__ void reduce_kernel(float* __restrict__ out) {
    __shared__ double sh[256];
    int tid = threadIdx.x;
    double s = 0.0;
    for (int i = tid; i < P_CHAINS; i += 256)
        s += (double)g_partial[i];
    sh[tid] = s;
    __syncthreads();
    for (int w = 128; w > 0; w >>= 1) {
        if (tid < w) sh[tid] += sh[tid + w];
        __syncthreads();
    }
    if (tid == 0) out[0] = (float)sh[0];
}

// ---------------------------------------------------------------------------
extern "C" void kernel_launch(void* const* d_in, const int* in_sizes, int n_in,
                              void* d_out, int out_size) {
    const float* u      = (const float*)d_in[0];
    const float* v      = (const float*)d_in[1];
    const float* omega  = (const float*)d_in[2];
    const float* A      = (const float*)d_in[3];
    const float* Blogit = (const float*)d_in[4];
    float* out = (float*)d_out;

    // Dynamic smem opt-in (host-side attribute, idempotent, not a stream op).
    cudaFuncSetAttribute(scan_kernel,
                         cudaFuncAttributeMaxDynamicSharedMemorySize,
                         (int)SMEM_BYTES);

    prep_kernel<<<T_LEN / (256 * 2), 256>>>(u, v);
    scan_kernel<<<NBLK, CPB, SMEM_BYTES>>>(omega, A, Blogit);
    reduce_kernel<<<1, 256>>>(out);
}